// round 8
// baseline (speedup 1.0000x reference)
#include <cuda_runtime.h>
#include <cstdint>

#define TT  50
#define FF  24
#define H1  64
#define LAT 32
#define H3  64
#define BMAX 8192

typedef unsigned long long u64;

__device__ float g_h1[(size_t)BMAX * TT * H1];   // [B][T][64]
__device__ float g_z [(size_t)BMAX * LAT];

__device__ __forceinline__ float sigmoidf(float v) {
    return __fdividef(1.0f, 1.0f + __expf(-v));
}
__device__ __forceinline__ u64 ffma2(u64 a, u64 b, u64 c) {
    u64 d; asm("fma.rn.f32x2 %0, %1, %2, %3;" : "=l"(d) : "l"(a), "l"(b), "l"(c)); return d;
}
__device__ __forceinline__ u64 pack2(float lo, float hi) {
    u64 r; asm("mov.b64 %0, {%1, %2};" : "=l"(r) : "f"(lo), "f"(hi)); return r;
}
__device__ __forceinline__ float2 unpack2(u64 v) {
    float2 f; asm("mov.b64 {%0, %1}, %2;" : "=f"(f.x), "=f"(f.y) : "l"(v)); return f;
}

// ---------------------------------------------------------------------------
// LSTM1: x[B,T,24] -> g_h1[B,T,64]
// 128 threads, C=2 columns per thread (cols 2j, 2j+1), R=8 rows per block.
// Occupancy cap raised to 3 CTAs/SM (<=170 regs) for latency hiding.
// ---------------------------------------------------------------------------
__global__ void __launch_bounds__(128, 3) lstm1_kernel(
    const float* __restrict__ x, const float* __restrict__ W,
    const float* __restrict__ U, const float* __restrict__ b, int B)
{
    constexpr int D = FF, H = H1, G = 4 * H1, R = 8;
    __shared__ __align__(16) float xs[2][R][D];
    __shared__ __align__(16) float hs[R][H];
    __shared__ __align__(16) float zs[R][G];

    const int j    = threadIdx.x;
    const int cA   = 2 * j, cB = 2 * j + 1;
    const int row0 = blockIdx.x * R;

    u64 wA[D / 2], wB[D / 2], uA[H / 2], uB[H / 2];
#pragma unroll
    for (int k = 0; k < D / 2; k++) {
        wA[k] = pack2(W[(2 * k) * G + cA], W[(2 * k + 1) * G + cA]);
        wB[k] = pack2(W[(2 * k) * G + cB], W[(2 * k + 1) * G + cB]);
    }
#pragma unroll
    for (int k = 0; k < H / 2; k++) {
        uA[k] = pack2(U[(2 * k) * G + cA], U[(2 * k + 1) * G + cA]);
        uB[k] = pack2(U[(2 * k) * G + cB], U[(2 * k + 1) * G + cB]);
    }
    const u64 bA = pack2(b[cA], 0.0f);
    const u64 bB = pack2(b[cB], 0.0f);

    for (int idx = j; idx < R * H; idx += 128) (&hs[0][0])[idx] = 0.0f;

    // gate tasks: 4 per thread. um = j&63, rows rbase+2q.
    const int um = j & (H - 1);
    const int rbase = j >> 6;          // 0..1
    float cst[4] = {0.0f, 0.0f, 0.0f, 0.0f};

    // x staging: 192 elements; thread j loads idx j and (j<64) idx j+128
    const int i0 = j, i1 = j + 128;
    const int lr0 = i0 / D, lk0 = i0 - lr0 * D;
    const int lr1 = i1 / D, lk1 = i1 - lr1 * D;
    float xr0 = 0.0f, xr1 = 0.0f;
    {
        int r0c = min(row0 + lr0, B - 1);
        xr0 = x[((size_t)r0c * TT + 0) * D + lk0];
        if (j < 64) {
            int r1c = min(row0 + lr1, B - 1);
            xr1 = x[((size_t)r1c * TT + 0) * D + lk1];
        }
    }

    int buf = 0;
    for (int t = 0; t < TT; t++) {
        xs[buf][lr0][lk0] = xr0;
        if (j < 64) xs[buf][lr1][lk1] = xr1;
        if (t + 1 < TT) {
            int r0c = min(row0 + lr0, B - 1);
            xr0 = x[((size_t)r0c * TT + (t + 1)) * D + lk0];
            if (j < 64) {
                int r1c = min(row0 + lr1, B - 1);
                xr1 = x[((size_t)r1c * TT + (t + 1)) * D + lk1];
            }
        }
        __syncthreads();   // A: xs + hs(t-1) visible

        u64 accA[R], accB[R];
#pragma unroll
        for (int r = 0; r < R; r++) { accA[r] = bA; accB[r] = bB; }
#pragma unroll
        for (int k = 0; k < D / 4; k++) {
#pragma unroll
            for (int r = 0; r < R; r++) {
                const ulonglong2 xv = *(const ulonglong2*)&xs[buf][r][4 * k];
                accA[r] = ffma2(xv.x, wA[2 * k], accA[r]);
                accA[r] = ffma2(xv.y, wA[2 * k + 1], accA[r]);
                accB[r] = ffma2(xv.x, wB[2 * k], accB[r]);
                accB[r] = ffma2(xv.y, wB[2 * k + 1], accB[r]);
            }
        }
#pragma unroll
        for (int k = 0; k < H / 4; k++) {
#pragma unroll
            for (int r = 0; r < R; r++) {
                const ulonglong2 hv = *(const ulonglong2*)&hs[r][4 * k];
                accA[r] = ffma2(hv.x, uA[2 * k], accA[r]);
                accA[r] = ffma2(hv.y, uA[2 * k + 1], accA[r]);
                accB[r] = ffma2(hv.x, uB[2 * k], accB[r]);
                accB[r] = ffma2(hv.y, uB[2 * k + 1], accB[r]);
            }
        }
#pragma unroll
        for (int r = 0; r < R; r++) {
            const float2 pA = unpack2(accA[r]);
            const float2 pB = unpack2(accB[r]);
            *(float2*)&zs[r][cA] = make_float2(pA.x + pA.y, pB.x + pB.y);
        }
        __syncthreads();   // B: zs ready, hs reads done

#pragma unroll
        for (int q = 0; q < 4; q++) {
            const int r = rbase + 2 * q;
            float zi = zs[r][um], zf = zs[r][H + um];
            float zg = zs[r][2 * H + um], zo = zs[r][3 * H + um];
            cst[q] = sigmoidf(zf) * cst[q] + sigmoidf(zi) * fmaxf(zg, 0.0f);
            float hn = sigmoidf(zo) * fmaxf(cst[q], 0.0f);
            hs[r][um] = hn;
            if (row0 + r < B) g_h1[((size_t)(row0 + r) * TT + t) * H + um] = hn;
        }
        buf ^= 1;
    }
}

// ---------------------------------------------------------------------------
// LSTM2: g_h1[B,T,64] -> g_z[B,32]. 64 threads, C=2, R=8. 6 CTAs/SM cap.
// ---------------------------------------------------------------------------
__global__ void __launch_bounds__(64, 6) lstm2_kernel(
    const float* __restrict__ W, const float* __restrict__ U,
    const float* __restrict__ b, int B)
{
    constexpr int D = H1, H = LAT, G = 4 * LAT, R = 8;
    __shared__ __align__(16) float xs[2][R][D];
    __shared__ __align__(16) float hs[R][H];
    __shared__ __align__(16) float zs[R][G];

    const int j    = threadIdx.x;
    const int cA   = 2 * j, cB = 2 * j + 1;
    const int row0 = blockIdx.x * R;

    u64 wA[D / 2], wB[D / 2], uA[H / 2], uB[H / 2];
#pragma unroll
    for (int k = 0; k < D / 2; k++) {
        wA[k] = pack2(W[(2 * k) * G + cA], W[(2 * k + 1) * G + cA]);
        wB[k] = pack2(W[(2 * k) * G + cB], W[(2 * k + 1) * G + cB]);
    }
#pragma unroll
    for (int k = 0; k < H / 2; k++) {
        uA[k] = pack2(U[(2 * k) * G + cA], U[(2 * k + 1) * G + cA]);
        uB[k] = pack2(U[(2 * k) * G + cB], U[(2 * k + 1) * G + cB]);
    }
    const u64 bA = pack2(b[cA], 0.0f);
    const u64 bB = pack2(b[cB], 0.0f);

    for (int idx = j; idx < R * H; idx += 64) (&hs[0][0])[idx] = 0.0f;

    const int um = j & (H - 1);
    const int rbase = j >> 5;          // 0..1
    float cst[4] = {0.0f, 0.0f, 0.0f, 0.0f};

    // staging: 512 floats / 64 threads = 8 each (2x float4)
    const int lr = j >> 3, lk = (j & 7) * 8;
    float4 xg0, xg1;
    {
        int row = min(row0 + lr, B - 1);
        const float4* p = (const float4*)&g_h1[((size_t)row * TT + 0) * D + lk];
        xg0 = p[0]; xg1 = p[1];
    }

    int buf = 0;
    for (int t = 0; t < TT; t++) {
        *(float4*)&xs[buf][lr][lk]     = xg0;
        *(float4*)&xs[buf][lr][lk + 4] = xg1;
        if (t + 1 < TT) {
            int row = min(row0 + lr, B - 1);
            const float4* p = (const float4*)&g_h1[((size_t)row * TT + (t + 1)) * D + lk];
            xg0 = p[0]; xg1 = p[1];
        }
        __syncthreads();

        u64 accA[R], accB[R];
#pragma unroll
        for (int r = 0; r < R; r++) { accA[r] = bA; accB[r] = bB; }
#pragma unroll
        for (int k = 0; k < D / 4; k++) {
#pragma unroll
            for (int r = 0; r < R; r++) {
                const ulonglong2 xv = *(const ulonglong2*)&xs[buf][r][4 * k];
                accA[r] = ffma2(xv.x, wA[2 * k], accA[r]);
                accA[r] = ffma2(xv.y, wA[2 * k + 1], accA[r]);
                accB[r] = ffma2(xv.x, wB[2 * k], accB[r]);
                accB[r] = ffma2(xv.y, wB[2 * k + 1], accB[r]);
            }
        }
#pragma unroll
        for (int k = 0; k < H / 4; k++) {
#pragma unroll
            for (int r = 0; r < R; r++) {
                const ulonglong2 hv = *(const ulonglong2*)&hs[r][4 * k];
                accA[r] = ffma2(hv.x, uA[2 * k], accA[r]);
                accA[r] = ffma2(hv.y, uA[2 * k + 1], accA[r]);
                accB[r] = ffma2(hv.x, uB[2 * k], accB[r]);
                accB[r] = ffma2(hv.y, uB[2 * k + 1], accB[r]);
            }
        }
#pragma unroll
        for (int r = 0; r < R; r++) {
            const float2 pA = unpack2(accA[r]);
            const float2 pB = unpack2(accB[r]);
            *(float2*)&zs[r][cA] = make_float2(pA.x + pA.y, pB.x + pB.y);
        }
        __syncthreads();

#pragma unroll
        for (int q = 0; q < 4; q++) {
            const int r = rbase + 2 * q;
            float zi = zs[r][um], zf = zs[r][H + um];
            float zg = zs[r][2 * H + um], zo = zs[r][3 * H + um];
            cst[q] = sigmoidf(zf) * cst[q] + sigmoidf(zi) * fmaxf(zg, 0.0f);
            float hn = sigmoidf(zo) * fmaxf(cst[q], 0.0f);
            hs[r][um] = hn;
            if (t == TT - 1 && row0 + r < B) g_z[(size_t)(row0 + r) * H + um] = hn;
        }
        buf ^= 1;
    }
}

// ---------------------------------------------------------------------------
// LSTM3 + TimeDistributed Dense: g_z[B,32] -> out[B,T,24]. 128 threads, C=2.
// 3 CTAs/SM cap.
// ---------------------------------------------------------------------------
__global__ void __launch_bounds__(128, 3) lstm3_kernel(
    const float* __restrict__ W, const float* __restrict__ U,
    const float* __restrict__ b, const float* __restrict__ Wd,
    const float* __restrict__ bd, float* __restrict__ out, int B)
{
    constexpr int D = LAT, H = H3, G = 4 * H3, R = 8;
    constexpr int WDP = 68;
    __shared__ __align__(16) float zin[R][D];
    __shared__ __align__(16) float hs[R][H];
    __shared__ __align__(16) float zb[R][G];
    __shared__ __align__(16) float wdst[FF][WDP];

    const int j    = threadIdx.x;
    const int cA   = 2 * j, cB = 2 * j + 1;
    const int row0 = blockIdx.x * R;

    u64 uA[H / 2], uB[H / 2];
#pragma unroll
    for (int k = 0; k < H / 2; k++) {
        uA[k] = pack2(U[(2 * k) * G + cA], U[(2 * k + 1) * G + cA]);
        uB[k] = pack2(U[(2 * k) * G + cB], U[(2 * k + 1) * G + cB]);
    }

    for (int idx = j; idx < H * FF; idx += 128) {
        int h = idx / FF, f = idx - h * FF;
        wdst[f][h] = Wd[idx];
    }
    for (int idx = j; idx < R * D; idx += 128) {
        int r = idx >> 5, k = idx & 31;
        int row = min(row0 + r, B - 1);
        zin[r][k] = g_z[(size_t)row * D + k];
    }
    for (int idx = j; idx < R * H; idx += 128) (&hs[0][0])[idx] = 0.0f;
    __syncthreads();

    // zw precompute (input constant over t): per col
    float zwA[R], zwB[R];
    {
        const float bvA = b[cA], bvB = b[cB];
#pragma unroll
        for (int r = 0; r < R; r++) { zwA[r] = bvA; zwB[r] = bvB; }
        for (int k = 0; k < D; k++) {
            const float wkA = W[k * G + cA], wkB = W[k * G + cB];
#pragma unroll
            for (int r = 0; r < R; r++) {
                zwA[r] += zin[r][k] * wkA;
                zwB[r] += zin[r][k] * wkB;
            }
        }
    }

    const int um = j & (H - 1);
    const int rbase = j >> 6;
    float cst[4] = {0.0f, 0.0f, 0.0f, 0.0f};

    // dense tasks: 192 over 128 threads: task j, and j+128 (j<64)
    const int d0f = j % FF, d0r = j / FF;
    const int d1f = (j + 128) % FF, d1r = (j + 128) / FF;
    const float bd0 = bd[d0f];
    const float bd1 = (j < 64) ? bd[d1f] : 0.0f;

    for (int t = 0; t < TT; t++) {
        u64 accA[R], accB[R];
#pragma unroll
        for (int r = 0; r < R; r++) {
            accA[r] = pack2(zwA[r], 0.0f);
            accB[r] = pack2(zwB[r], 0.0f);
        }
#pragma unroll
        for (int k = 0; k < H / 4; k++) {
#pragma unroll
            for (int r = 0; r < R; r++) {
                const ulonglong2 hv = *(const ulonglong2*)&hs[r][4 * k];
                accA[r] = ffma2(hv.x, uA[2 * k], accA[r]);
                accA[r] = ffma2(hv.y, uA[2 * k + 1], accA[r]);
                accB[r] = ffma2(hv.x, uB[2 * k], accB[r]);
                accB[r] = ffma2(hv.y, uB[2 * k + 1], accB[r]);
            }
        }
#pragma unroll
        for (int r = 0; r < R; r++) {
            const float2 pA = unpack2(accA[r]);
            const float2 pB = unpack2(accB[r]);
            *(float2*)&zb[r][cA] = make_float2(pA.x + pA.y, pB.x + pB.y);
        }
        __syncthreads();   // S2: zb ready, hs reads done

#pragma unroll
        for (int q = 0; q < 4; q++) {
            const int r = rbase + 2 * q;
            float zi = zb[r][um], zf = zb[r][H + um];
            float zg = zb[r][2 * H + um], zo = zb[r][3 * H + um];
            cst[q] = sigmoidf(zf) * cst[q] + sigmoidf(zi) * fmaxf(zg, 0.0f);
            float hn = sigmoidf(zo) * fmaxf(cst[q], 0.0f);
            hs[r][um] = hn;
        }
        __syncthreads();   // S3: hs(t) visible

        // dense
        {
            int row = row0 + d0r;
            if (row < B) {
                u64 sacc = pack2(bd0, 0.0f);
#pragma unroll
                for (int k = 0; k < H / 4; k++) {
                    const ulonglong2 hv = *(const ulonglong2*)&hs[d0r][4 * k];
                    const ulonglong2 wv = *(const ulonglong2*)&wdst[d0f][4 * k];
                    sacc = ffma2(hv.x, wv.x, sacc);
                    sacc = ffma2(hv.y, wv.y, sacc);
                }
                const float2 p = unpack2(sacc);
                out[((size_t)row * TT + t) * FF + d0f] = p.x + p.y;
            }
        }
        if (j < 64) {
            int row = row0 + d1r;
            if (row < B) {
                u64 sacc = pack2(bd1, 0.0f);
#pragma unroll
                for (int k = 0; k < H / 4; k++) {
                    const ulonglong2 hv = *(const ulonglong2*)&hs[d1r][4 * k];
                    const ulonglong2 wv = *(const ulonglong2*)&wdst[d1f][4 * k];
                    sacc = ffma2(hv.x, wv.x, sacc);
                    sacc = ffma2(hv.y, wv.y, sacc);
                }
                const float2 p = unpack2(sacc);
                out[((size_t)row * TT + t) * FF + d1f] = p.x + p.y;
            }
        }
    }
}

// ---------------------------------------------------------------------------
extern "C" void kernel_launch(void* const* d_in, const int* in_sizes, int n_in,
                              void* d_out, int out_size)
{
    const float* x  = (const float*)d_in[0];
    const float* W1 = (const float*)d_in[1];
    const float* U1 = (const float*)d_in[2];
    const float* b1 = (const float*)d_in[3];
    const float* W2 = (const float*)d_in[4];
    const float* U2 = (const float*)d_in[5];
    const float* b2 = (const float*)d_in[6];
    const float* W3 = (const float*)d_in[7];
    const float* U3 = (const float*)d_in[8];
    const float* b3 = (const float*)d_in[9];
    const float* Wd = (const float*)d_in[10];
    const float* bd = (const float*)d_in[11];
    float* out = (float*)d_out;

    const int B = in_sizes[0] / (TT * FF);
    const int nblk = (B + 7) / 8;

    lstm1_kernel<<<nblk, 128>>>(x, W1, U1, b1, B);
    lstm2_kernel<<<nblk, 64>>>(W2, U2, b2, B);
    lstm3_kernel<<<nblk, 128>>>(W3, U3, b3, Wd, bd, out, B);
}

// round 9
// speedup vs baseline: 1.7933x; 1.7933x over previous
#include <cuda_runtime.h>
#include <cstdint>

#define TT  50
#define FF  24
#define H1  64
#define LAT 32
#define H3  64
#define BMAX 8192

typedef unsigned long long u64;

__device__ float g_h1[(size_t)BMAX * TT * H1];   // [B][T][64]
__device__ float g_z [(size_t)BMAX * LAT];

__device__ __forceinline__ float sigmoidf(float v) {
    return __fdividef(1.0f, 1.0f + __expf(-v));
}
__device__ __forceinline__ u64 ffma2(u64 a, u64 b, u64 c) {
    u64 d; asm("fma.rn.f32x2 %0, %1, %2, %3;" : "=l"(d) : "l"(a), "l"(b), "l"(c)); return d;
}
__device__ __forceinline__ u64 pack2(float lo, float hi) {
    u64 r; asm("mov.b64 %0, {%1, %2};" : "=l"(r) : "f"(lo), "f"(hi)); return r;
}
__device__ __forceinline__ float2 unpack2(u64 v) {
    float2 f; asm("mov.b64 {%0, %1}, %2;" : "=f"(f.x), "=f"(f.y) : "l"(v)); return f;
}

// ---------------------------------------------------------------------------
// LSTM1: x[B,T,24] -> g_h1[B,T,64]
// 128 threads, C=2 cols/thread, R=8 rows/block. Gate-interleaved z layout:
// interleaved col c = 4*unit + gate; thread j owns c = 2j, 2j+1
// (gates {0,1} or {2,3} of unit j>>1). Gate task reads ONE LDS.128.
// ---------------------------------------------------------------------------
__global__ void __launch_bounds__(128, 2) lstm1_kernel(
    const float* __restrict__ x, const float* __restrict__ W,
    const float* __restrict__ U, const float* __restrict__ b, int B)
{
    constexpr int D = FF, H = H1, G = 4 * H1, R = 8;
    __shared__ __align__(16) float xs[2][R][D];
    __shared__ __align__(16) float hs[R][H];
    __shared__ __align__(16) float zs[R][G];

    const int j    = threadIdx.x;
    const int cA   = 2 * j;
    const int uu   = j >> 1;                 // unit for this thread's cols
    const int gA   = cA & 3;                 // gate of col cA (0 or 2)
    const int sA   = gA * H + uu;            // source col in W/U/b
    const int sB   = (gA + 1) * H + uu;
    const int row0 = blockIdx.x * R;

    u64 wA[D / 2], wB[D / 2], uA[H / 2], uB[H / 2];
#pragma unroll
    for (int k = 0; k < D / 2; k++) {
        wA[k] = pack2(W[(2 * k) * G + sA], W[(2 * k + 1) * G + sA]);
        wB[k] = pack2(W[(2 * k) * G + sB], W[(2 * k + 1) * G + sB]);
    }
#pragma unroll
    for (int k = 0; k < H / 2; k++) {
        uA[k] = pack2(U[(2 * k) * G + sA], U[(2 * k + 1) * G + sA]);
        uB[k] = pack2(U[(2 * k) * G + sB], U[(2 * k + 1) * G + sB]);
    }
    const u64 bA = pack2(b[sA], 0.0f);
    const u64 bB = pack2(b[sB], 0.0f);

    for (int idx = j; idx < R * H; idx += 128) (&hs[0][0])[idx] = 0.0f;

    // gate tasks: 4 per thread, unit um, rows rbase+2q
    const int um = j & (H - 1);
    const int rbase = j >> 6;          // 0..1
    float cst[4] = {0.0f, 0.0f, 0.0f, 0.0f};

    // x staging: 192 elements; thread j loads idx j and (j<64) idx j+128
    const int i0 = j, i1 = j + 128;
    const int lr0 = i0 / D, lk0 = i0 - lr0 * D;
    const int lr1 = i1 / D, lk1 = i1 - lr1 * D;
    float xr0 = 0.0f, xr1 = 0.0f;
    {
        int r0c = min(row0 + lr0, B - 1);
        xr0 = x[((size_t)r0c * TT + 0) * D + lk0];
        if (j < 64) {
            int r1c = min(row0 + lr1, B - 1);
            xr1 = x[((size_t)r1c * TT + 0) * D + lk1];
        }
    }

    int buf = 0;
    for (int t = 0; t < TT; t++) {
        xs[buf][lr0][lk0] = xr0;
        if (j < 64) xs[buf][lr1][lk1] = xr1;
        if (t + 1 < TT) {
            int r0c = min(row0 + lr0, B - 1);
            xr0 = x[((size_t)r0c * TT + (t + 1)) * D + lk0];
            if (j < 64) {
                int r1c = min(row0 + lr1, B - 1);
                xr1 = x[((size_t)r1c * TT + (t + 1)) * D + lk1];
            }
        }
        __syncthreads();   // A: xs + hs(t-1) visible

        u64 accA[R], accB[R];
#pragma unroll
        for (int r = 0; r < R; r++) { accA[r] = bA; accB[r] = bB; }
#pragma unroll
        for (int k = 0; k < D / 4; k++) {
#pragma unroll
            for (int r = 0; r < R; r++) {
                const ulonglong2 xv = *(const ulonglong2*)&xs[buf][r][4 * k];
                accA[r] = ffma2(xv.x, wA[2 * k], accA[r]);
                accA[r] = ffma2(xv.y, wA[2 * k + 1], accA[r]);
                accB[r] = ffma2(xv.x, wB[2 * k], accB[r]);
                accB[r] = ffma2(xv.y, wB[2 * k + 1], accB[r]);
            }
        }
#pragma unroll
        for (int k = 0; k < H / 4; k++) {
#pragma unroll
            for (int r = 0; r < R; r++) {
                const ulonglong2 hv = *(const ulonglong2*)&hs[r][4 * k];
                accA[r] = ffma2(hv.x, uA[2 * k], accA[r]);
                accA[r] = ffma2(hv.y, uA[2 * k + 1], accA[r]);
                accB[r] = ffma2(hv.x, uB[2 * k], accB[r]);
                accB[r] = ffma2(hv.y, uB[2 * k + 1], accB[r]);
            }
        }
#pragma unroll
        for (int r = 0; r < R; r++) {
            const float2 pA = unpack2(accA[r]);
            const float2 pB = unpack2(accB[r]);
            *(float2*)&zs[r][cA] = make_float2(pA.x + pA.y, pB.x + pB.y);
        }
        __syncthreads();   // B: zs ready, hs reads done

#pragma unroll
        for (int q = 0; q < 4; q++) {
            const int r = rbase + 2 * q;
            const float4 zv = *(const float4*)&zs[r][4 * um];   // i,f,g,o
            cst[q] = sigmoidf(zv.y) * cst[q] + sigmoidf(zv.x) * fmaxf(zv.z, 0.0f);
            float hn = sigmoidf(zv.w) * fmaxf(cst[q], 0.0f);
            hs[r][um] = hn;
            if (row0 + r < B) g_h1[((size_t)(row0 + r) * TT + t) * H + um] = hn;
        }
        buf ^= 1;
    }
}

// ---------------------------------------------------------------------------
// LSTM2: g_h1[B,T,64] -> g_z[B,32]. 64 threads, C=2, R=8, gate-interleaved.
// ---------------------------------------------------------------------------
__global__ void __launch_bounds__(64, 4) lstm2_kernel(
    const float* __restrict__ W, const float* __restrict__ U,
    const float* __restrict__ b, int B)
{
    constexpr int D = H1, H = LAT, G = 4 * LAT, R = 8;
    __shared__ __align__(16) float xs[2][R][D];
    __shared__ __align__(16) float hs[R][H];
    __shared__ __align__(16) float zs[R][G];

    const int j    = threadIdx.x;
    const int cA   = 2 * j;
    const int uu   = j >> 1;
    const int gA   = cA & 3;
    const int sA   = gA * H + uu;
    const int sB   = (gA + 1) * H + uu;
    const int row0 = blockIdx.x * R;

    u64 wA[D / 2], wB[D / 2], uA[H / 2], uB[H / 2];
#pragma unroll
    for (int k = 0; k < D / 2; k++) {
        wA[k] = pack2(W[(2 * k) * G + sA], W[(2 * k + 1) * G + sA]);
        wB[k] = pack2(W[(2 * k) * G + sB], W[(2 * k + 1) * G + sB]);
    }
#pragma unroll
    for (int k = 0; k < H / 2; k++) {
        uA[k] = pack2(U[(2 * k) * G + sA], U[(2 * k + 1) * G + sA]);
        uB[k] = pack2(U[(2 * k) * G + sB], U[(2 * k + 1) * G + sB]);
    }
    const u64 bA = pack2(b[sA], 0.0f);
    const u64 bB = pack2(b[sB], 0.0f);

    for (int idx = j; idx < R * H; idx += 64) (&hs[0][0])[idx] = 0.0f;

    const int um = j & (H - 1);
    const int rbase = j >> 5;          // 0..1
    float cst[4] = {0.0f, 0.0f, 0.0f, 0.0f};

    // staging: 512 floats / 64 threads = 8 each (2x float4)
    const int lr = j >> 3, lk = (j & 7) * 8;
    float4 xg0, xg1;
    {
        int row = min(row0 + lr, B - 1);
        const float4* p = (const float4*)&g_h1[((size_t)row * TT + 0) * D + lk];
        xg0 = p[0]; xg1 = p[1];
    }

    int buf = 0;
    for (int t = 0; t < TT; t++) {
        *(float4*)&xs[buf][lr][lk]     = xg0;
        *(float4*)&xs[buf][lr][lk + 4] = xg1;
        if (t + 1 < TT) {
            int row = min(row0 + lr, B - 1);
            const float4* p = (const float4*)&g_h1[((size_t)row * TT + (t + 1)) * D + lk];
            xg0 = p[0]; xg1 = p[1];
        }
        __syncthreads();

        u64 accA[R], accB[R];
#pragma unroll
        for (int r = 0; r < R; r++) { accA[r] = bA; accB[r] = bB; }
#pragma unroll
        for (int k = 0; k < D / 4; k++) {
#pragma unroll
            for (int r = 0; r < R; r++) {
                const ulonglong2 xv = *(const ulonglong2*)&xs[buf][r][4 * k];
                accA[r] = ffma2(xv.x, wA[2 * k], accA[r]);
                accA[r] = ffma2(xv.y, wA[2 * k + 1], accA[r]);
                accB[r] = ffma2(xv.x, wB[2 * k], accB[r]);
                accB[r] = ffma2(xv.y, wB[2 * k + 1], accB[r]);
            }
        }
#pragma unroll
        for (int k = 0; k < H / 4; k++) {
#pragma unroll
            for (int r = 0; r < R; r++) {
                const ulonglong2 hv = *(const ulonglong2*)&hs[r][4 * k];
                accA[r] = ffma2(hv.x, uA[2 * k], accA[r]);
                accA[r] = ffma2(hv.y, uA[2 * k + 1], accA[r]);
                accB[r] = ffma2(hv.x, uB[2 * k], accB[r]);
                accB[r] = ffma2(hv.y, uB[2 * k + 1], accB[r]);
            }
        }
#pragma unroll
        for (int r = 0; r < R; r++) {
            const float2 pA = unpack2(accA[r]);
            const float2 pB = unpack2(accB[r]);
            *(float2*)&zs[r][cA] = make_float2(pA.x + pA.y, pB.x + pB.y);
        }
        __syncthreads();

#pragma unroll
        for (int q = 0; q < 4; q++) {
            const int r = rbase + 2 * q;
            const float4 zv = *(const float4*)&zs[r][4 * um];
            cst[q] = sigmoidf(zv.y) * cst[q] + sigmoidf(zv.x) * fmaxf(zv.z, 0.0f);
            float hn = sigmoidf(zv.w) * fmaxf(cst[q], 0.0f);
            hs[r][um] = hn;
            if (t == TT - 1 && row0 + r < B) g_z[(size_t)(row0 + r) * H + um] = hn;
        }
        buf ^= 1;
    }
}

// ---------------------------------------------------------------------------
// LSTM3 + TimeDistributed Dense: g_z[B,32] -> out[B,T,24].
// 128 threads, C=2, gate-interleaved z layout.
// ---------------------------------------------------------------------------
__global__ void __launch_bounds__(128, 2) lstm3_kernel(
    const float* __restrict__ W, const float* __restrict__ U,
    const float* __restrict__ b, const float* __restrict__ Wd,
    const float* __restrict__ bd, float* __restrict__ out, int B)
{
    constexpr int D = LAT, H = H3, G = 4 * H3, R = 8;
    constexpr int WDP = 68;
    __shared__ __align__(16) float zin[R][D];
    __shared__ __align__(16) float hs[R][H];
    __shared__ __align__(16) float zb[R][G];
    __shared__ __align__(16) float wdst[FF][WDP];

    const int j    = threadIdx.x;
    const int cA   = 2 * j;
    const int uu   = j >> 1;
    const int gA   = cA & 3;
    const int sA   = gA * H + uu;
    const int sB   = (gA + 1) * H + uu;
    const int row0 = blockIdx.x * R;

    u64 uA[H / 2], uB[H / 2];
#pragma unroll
    for (int k = 0; k < H / 2; k++) {
        uA[k] = pack2(U[(2 * k) * G + sA], U[(2 * k + 1) * G + sA]);
        uB[k] = pack2(U[(2 * k) * G + sB], U[(2 * k + 1) * G + sB]);
    }

    for (int idx = j; idx < H * FF; idx += 128) {
        int h = idx / FF, f = idx - h * FF;
        wdst[f][h] = Wd[idx];
    }
    for (int idx = j; idx < R * D; idx += 128) {
        int r = idx >> 5, k = idx & 31;
        int row = min(row0 + r, B - 1);
        zin[r][k] = g_z[(size_t)row * D + k];
    }
    for (int idx = j; idx < R * H; idx += 128) (&hs[0][0])[idx] = 0.0f;
    __syncthreads();

    // zw precompute (input constant over t): per interleaved col
    float zwA[R], zwB[R];
    {
        const float bvA = b[sA], bvB = b[sB];
#pragma unroll
        for (int r = 0; r < R; r++) { zwA[r] = bvA; zwB[r] = bvB; }
        for (int k = 0; k < D; k++) {
            const float wkA = W[k * G + sA], wkB = W[k * G + sB];
#pragma unroll
            for (int r = 0; r < R; r++) {
                zwA[r] += zin[r][k] * wkA;
                zwB[r] += zin[r][k] * wkB;
            }
        }
    }

    const int um = j & (H - 1);
    const int rbase = j >> 6;
    float cst[4] = {0.0f, 0.0f, 0.0f, 0.0f};

    // dense tasks: 192 over 128 threads: task j, and j+128 (j<64)
    const int d0f = j % FF, d0r = j / FF;
    const int d1f = (j + 128) % FF, d1r = (j + 128) / FF;
    const float bd0 = bd[d0f];
    const float bd1 = (j < 64) ? bd[d1f] : 0.0f;

    for (int t = 0; t < TT; t++) {
        u64 accA[R], accB[R];
#pragma unroll
        for (int r = 0; r < R; r++) {
            accA[r] = pack2(zwA[r], 0.0f);
            accB[r] = pack2(zwB[r], 0.0f);
        }
#pragma unroll
        for (int k = 0; k < H / 4; k++) {
#pragma unroll
            for (int r = 0; r < R; r++) {
                const ulonglong2 hv = *(const ulonglong2*)&hs[r][4 * k];
                accA[r] = ffma2(hv.x, uA[2 * k], accA[r]);
                accA[r] = ffma2(hv.y, uA[2 * k + 1], accA[r]);
                accB[r] = ffma2(hv.x, uB[2 * k], accB[r]);
                accB[r] = ffma2(hv.y, uB[2 * k + 1], accB[r]);
            }
        }
#pragma unroll
        for (int r = 0; r < R; r++) {
            const float2 pA = unpack2(accA[r]);
            const float2 pB = unpack2(accB[r]);
            *(float2*)&zb[r][cA] = make_float2(pA.x + pA.y, pB.x + pB.y);
        }
        __syncthreads();   // S2: zb ready, hs reads done

#pragma unroll
        for (int q = 0; q < 4; q++) {
            const int r = rbase + 2 * q;
            const float4 zv = *(const float4*)&zb[r][4 * um];
            cst[q] = sigmoidf(zv.y) * cst[q] + sigmoidf(zv.x) * fmaxf(zv.z, 0.0f);
            float hn = sigmoidf(zv.w) * fmaxf(cst[q], 0.0f);
            hs[r][um] = hn;
        }
        __syncthreads();   // S3: hs(t) visible

        // dense
        {
            int row = row0 + d0r;
            if (row < B) {
                u64 sacc = pack2(bd0, 0.0f);
#pragma unroll
                for (int k = 0; k < H / 4; k++) {
                    const ulonglong2 hv = *(const ulonglong2*)&hs[d0r][4 * k];
                    const ulonglong2 wv = *(const ulonglong2*)&wdst[d0f][4 * k];
                    sacc = ffma2(hv.x, wv.x, sacc);
                    sacc = ffma2(hv.y, wv.y, sacc);
                }
                const float2 p = unpack2(sacc);
                out[((size_t)row * TT + t) * FF + d0f] = p.x + p.y;
            }
        }
        if (j < 64) {
            int row = row0 + d1r;
            if (row < B) {
                u64 sacc = pack2(bd1, 0.0f);
#pragma unroll
                for (int k = 0; k < H / 4; k++) {
                    const ulonglong2 hv = *(const ulonglong2*)&hs[d1r][4 * k];
                    const ulonglong2 wv = *(const ulonglong2*)&wdst[d1f][4 * k];
                    sacc = ffma2(hv.x, wv.x, sacc);
                    sacc = ffma2(hv.y, wv.y, sacc);
                }
                const float2 p = unpack2(sacc);
                out[((size_t)row * TT + t) * FF + d1f] = p.x + p.y;
            }
        }
    }
}

// ---------------------------------------------------------------------------
extern "C" void kernel_launch(void* const* d_in, const int* in_sizes, int n_in,
                              void* d_out, int out_size)
{
    const float* x  = (const float*)d_in[0];
    const float* W1 = (const float*)d_in[1];
    const float* U1 = (const float*)d_in[2];
    const float* b1 = (const float*)d_in[3];
    const float* W2 = (const float*)d_in[4];
    const float* U2 = (const float*)d_in[5];
    const float* b2 = (const float*)d_in[6];
    const float* W3 = (const float*)d_in[7];
    const float* U3 = (const float*)d_in[8];
    const float* b3 = (const float*)d_in[9];
    const float* Wd = (const float*)d_in[10];
    const float* bd = (const float*)d_in[11];
    float* out = (float*)d_out;

    const int B = in_sizes[0] / (TT * FF);
    const int nblk = (B + 7) / 8;

    lstm1_kernel<<<nblk, 128>>>(x, W1, U1, b1, B);
    lstm2_kernel<<<nblk, 64>>>(W2, U2, b2, B);
    lstm3_kernel<<<nblk, 128>>>(W3, U3, b3, Wd, bd, out, B);
}

// round 14
// speedup vs baseline: 1.9055x; 1.0626x over previous
#include <cuda_runtime.h>
#include <cstdint>

#define TT  50
#define FF  24
#define H1  64
#define LAT 32
#define H3  64
#define BMAX 8192

typedef unsigned long long u64;

__device__ float g_h1[(size_t)BMAX * TT * H1];   // [B][T][64]
__device__ float g_z [(size_t)BMAX * LAT];

__device__ __forceinline__ float sigmoidf(float v) {
    return __fdividef(1.0f, 1.0f + __expf(-v));
}
__device__ __forceinline__ u64 ffma2(u64 a, u64 b, u64 c) {
    u64 d; asm("fma.rn.f32x2 %0, %1, %2, %3;" : "=l"(d) : "l"(a), "l"(b), "l"(c)); return d;
}
__device__ __forceinline__ u64 pack2(float lo, float hi) {
    u64 r; asm("mov.b64 %0, {%1, %2};" : "=l"(r) : "f"(lo), "f"(hi)); return r;
}
__device__ __forceinline__ float2 unpack2(u64 v) {
    float2 f; asm("mov.b64 {%0, %1}, %2;" : "=f"(f.x), "=f"(f.y) : "l"(v)); return f;
}

// ---------------------------------------------------------------------------
// LSTM1: x[B,T,24] -> g_h1[B,T,64]
// 128 threads, C=2 cols/thread, R=8, gate-interleaved cols (c = 4u+g).
// Thread pair (2u, 2u+1) holds gates {i,f} / {g,o} of unit u; the gate
// exchange is 8 warp shuffles -> barrier B eliminated. hs double-buffered;
// ONE __syncthreads per timestep.
// ---------------------------------------------------------------------------
__global__ void __launch_bounds__(128, 2) lstm1_kernel(
    const float* __restrict__ x, const float* __restrict__ W,
    const float* __restrict__ U, const float* __restrict__ b, int B)
{
    constexpr int D = FF, H = H1, G = 4 * H1, R = 8;
    __shared__ __align__(16) float xs[2][R][D];
    __shared__ __align__(16) float hs[2][R][H];

    const int j    = threadIdx.x;
    const int uu   = j >> 1;                 // unit
    const int par  = j & 1;                  // 0: gates i,f   1: gates g,o
    const int sA   = (2 * par) * H + uu;     // source col in W/U/b
    const int sB   = (2 * par + 1) * H + uu;
    const int row0 = blockIdx.x * R;
    const int rlo  = 4 * par;                // rows owned for cell update

    u64 wA[D / 2], wB[D / 2], uA[H / 2], uB[H / 2];
#pragma unroll
    for (int k = 0; k < D / 2; k++) {
        wA[k] = pack2(W[(2 * k) * G + sA], W[(2 * k + 1) * G + sA]);
        wB[k] = pack2(W[(2 * k) * G + sB], W[(2 * k + 1) * G + sB]);
    }
#pragma unroll
    for (int k = 0; k < H / 2; k++) {
        uA[k] = pack2(U[(2 * k) * G + sA], U[(2 * k + 1) * G + sA]);
        uB[k] = pack2(U[(2 * k) * G + sB], U[(2 * k + 1) * G + sB]);
    }
    const u64 bA = pack2(b[sA], 0.0f);
    const u64 bB = pack2(b[sB], 0.0f);

    for (int idx = j; idx < R * H; idx += 128) (&hs[0][0][0])[idx] = 0.0f;

    float cst[4] = {0.0f, 0.0f, 0.0f, 0.0f};

    // x staging: 192 elems; thread j loads idx j and (j<64) idx j+128
    const int i0 = j, i1 = j + 128;
    const int lr0 = i0 / D, lk0 = i0 - lr0 * D;
    const int lr1 = i1 / D, lk1 = i1 - lr1 * D;
    float xr0 = 0.0f, xr1 = 0.0f;
    {
        int r0c = min(row0 + lr0, B - 1);
        xr0 = x[((size_t)r0c * TT + 0) * D + lk0];
        if (j < 64) {
            int r1c = min(row0 + lr1, B - 1);
            xr1 = x[((size_t)r1c * TT + 0) * D + lk1];
        }
    }

    int buf = 0, hb = 0;
    for (int t = 0; t < TT; t++) {
        xs[buf][lr0][lk0] = xr0;
        if (j < 64) xs[buf][lr1][lk1] = xr1;
        if (t + 1 < TT) {
            int r0c = min(row0 + lr0, B - 1);
            xr0 = x[((size_t)r0c * TT + (t + 1)) * D + lk0];
            if (j < 64) {
                int r1c = min(row0 + lr1, B - 1);
                xr1 = x[((size_t)r1c * TT + (t + 1)) * D + lk1];
            }
        }
        __syncthreads();   // A: xs(t) + hs[hb]=h(t-1) visible; prior reads of hs[hb^1] done

        u64 accA[R], accB[R];
#pragma unroll
        for (int r = 0; r < R; r++) { accA[r] = bA; accB[r] = bB; }
#pragma unroll
        for (int k = 0; k < D / 4; k++) {
#pragma unroll
            for (int r = 0; r < R; r++) {
                const ulonglong2 xv = *(const ulonglong2*)&xs[buf][r][4 * k];
                accA[r] = ffma2(xv.x, wA[2 * k], accA[r]);
                accA[r] = ffma2(xv.y, wA[2 * k + 1], accA[r]);
                accB[r] = ffma2(xv.x, wB[2 * k], accB[r]);
                accB[r] = ffma2(xv.y, wB[2 * k + 1], accB[r]);
            }
        }
#pragma unroll
        for (int k = 0; k < H / 4; k++) {
#pragma unroll
            for (int r = 0; r < R; r++) {
                const ulonglong2 hv = *(const ulonglong2*)&hs[hb][r][4 * k];
                accA[r] = ffma2(hv.x, uA[2 * k], accA[r]);
                accA[r] = ffma2(hv.y, uA[2 * k + 1], accA[r]);
                accB[r] = ffma2(hv.x, uB[2 * k], accB[r]);
                accB[r] = ffma2(hv.y, uB[2 * k + 1], accB[r]);
            }
        }
        float zA[R], zB[R];
#pragma unroll
        for (int r = 0; r < R; r++) {
            const float2 pA = unpack2(accA[r]);
            const float2 pB = unpack2(accB[r]);
            zA[r] = pA.x + pA.y;
            zB[r] = pB.x + pB.y;
        }
        // gate exchange within thread pair (no barrier): 8 shuffles
        float rA[4], rB[4];
#pragma unroll
        for (int k = 0; k < 4; k++) {
            float tA = par ? zA[k] : zA[k + 4];
            float tB = par ? zB[k] : zB[k + 4];
            rA[k] = __shfl_xor_sync(0xFFFFFFFFu, tA, 1);
            rB[k] = __shfl_xor_sync(0xFFFFFFFFu, tB, 1);
        }
#pragma unroll
        for (int k = 0; k < 4; k++) {
            const int r = rlo + k;
            const float iv = par ? rA[k] : zA[r];
            const float fv = par ? rB[k] : zB[r];
            const float gv = par ? zA[r] : rA[k];
            const float ov = par ? zB[r] : rB[k];
            cst[k] = sigmoidf(fv) * cst[k] + sigmoidf(iv) * fmaxf(gv, 0.0f);
            const float hn = sigmoidf(ov) * fmaxf(cst[k], 0.0f);
            hs[hb ^ 1][r][uu] = hn;
            if (row0 + r < B) g_h1[((size_t)(row0 + r) * TT + t) * H + uu] = hn;
        }
        buf ^= 1; hb ^= 1;
    }
}

// ---------------------------------------------------------------------------
// LSTM2: g_h1[B,T,64] -> g_z[B,32]. 64 threads, C=2, R=8, shuffle gates,
// double-buffered hs, one barrier per step.
// ---------------------------------------------------------------------------
__global__ void __launch_bounds__(64, 4) lstm2_kernel(
    const float* __restrict__ W, const float* __restrict__ U,
    const float* __restrict__ b, int B)
{
    constexpr int D = H1, H = LAT, G = 4 * LAT, R = 8;
    __shared__ __align__(16) float xs[2][R][D];
    __shared__ __align__(16) float hs[2][R][H];

    const int j    = threadIdx.x;
    const int uu   = j >> 1;
    const int par  = j & 1;
    const int sA   = (2 * par) * H + uu;
    const int sB   = (2 * par + 1) * H + uu;
    const int row0 = blockIdx.x * R;
    const int rlo  = 4 * par;

    u64 wA[D / 2], wB[D / 2], uA[H / 2], uB[H / 2];
#pragma unroll
    for (int k = 0; k < D / 2; k++) {
        wA[k] = pack2(W[(2 * k) * G + sA], W[(2 * k + 1) * G + sA]);
        wB[k] = pack2(W[(2 * k) * G + sB], W[(2 * k + 1) * G + sB]);
    }
#pragma unroll
    for (int k = 0; k < H / 2; k++) {
        uA[k] = pack2(U[(2 * k) * G + sA], U[(2 * k + 1) * G + sA]);
        uB[k] = pack2(U[(2 * k) * G + sB], U[(2 * k + 1) * G + sB]);
    }
    const u64 bA = pack2(b[sA], 0.0f);
    const u64 bB = pack2(b[sB], 0.0f);

    for (int idx = j; idx < R * H; idx += 64) (&hs[0][0][0])[idx] = 0.0f;

    float cst[4] = {0.0f, 0.0f, 0.0f, 0.0f};

    // staging: 512 floats / 64 threads = 8 each (2x float4)
    const int lr = j >> 3, lk = (j & 7) * 8;
    float4 xg0, xg1;
    {
        int row = min(row0 + lr, B - 1);
        const float4* p = (const float4*)&g_h1[((size_t)row * TT + 0) * D + lk];
        xg0 = p[0]; xg1 = p[1];
    }

    int buf = 0, hb = 0;
    for (int t = 0; t < TT; t++) {
        *(float4*)&xs[buf][lr][lk]     = xg0;
        *(float4*)&xs[buf][lr][lk + 4] = xg1;
        if (t + 1 < TT) {
            int row = min(row0 + lr, B - 1);
            const float4* p = (const float4*)&g_h1[((size_t)row * TT + (t + 1)) * D + lk];
            xg0 = p[0]; xg1 = p[1];
        }
        __syncthreads();

        u64 accA[R], accB[R];
#pragma unroll
        for (int r = 0; r < R; r++) { accA[r] = bA; accB[r] = bB; }
#pragma unroll
        for (int k = 0; k < D / 4; k++) {
#pragma unroll
            for (int r = 0; r < R; r++) {
                const ulonglong2 xv = *(const ulonglong2*)&xs[buf][r][4 * k];
                accA[r] = ffma2(xv.x, wA[2 * k], accA[r]);
                accA[r] = ffma2(xv.y, wA[2 * k + 1], accA[r]);
                accB[r] = ffma2(xv.x, wB[2 * k], accB[r]);
                accB[r] = ffma2(xv.y, wB[2 * k + 1], accB[r]);
            }
        }
#pragma unroll
        for (int k = 0; k < H / 4; k++) {
#pragma unroll
            for (int r = 0; r < R; r++) {
                const ulonglong2 hv = *(const ulonglong2*)&hs[hb][r][4 * k];
                accA[r] = ffma2(hv.x, uA[2 * k], accA[r]);
                accA[r] = ffma2(hv.y, uA[2 * k + 1], accA[r]);
                accB[r] = ffma2(hv.x, uB[2 * k], accB[r]);
                accB[r] = ffma2(hv.y, uB[2 * k + 1], accB[r]);
            }
        }
        float zA[R], zB[R];
#pragma unroll
        for (int r = 0; r < R; r++) {
            const float2 pA = unpack2(accA[r]);
            const float2 pB = unpack2(accB[r]);
            zA[r] = pA.x + pA.y;
            zB[r] = pB.x + pB.y;
        }
        float rA[4], rB[4];
#pragma unroll
        for (int k = 0; k < 4; k++) {
            float tA = par ? zA[k] : zA[k + 4];
            float tB = par ? zB[k] : zB[k + 4];
            rA[k] = __shfl_xor_sync(0xFFFFFFFFu, tA, 1);
            rB[k] = __shfl_xor_sync(0xFFFFFFFFu, tB, 1);
        }
#pragma unroll
        for (int k = 0; k < 4; k++) {
            const int r = rlo + k;
            const float iv = par ? rA[k] : zA[r];
            const float fv = par ? rB[k] : zB[r];
            const float gv = par ? zA[r] : rA[k];
            const float ov = par ? zB[r] : rB[k];
            cst[k] = sigmoidf(fv) * cst[k] + sigmoidf(iv) * fmaxf(gv, 0.0f);
            const float hn = sigmoidf(ov) * fmaxf(cst[k], 0.0f);
            hs[hb ^ 1][r][uu] = hn;
            if (t == TT - 1 && row0 + r < B) g_z[(size_t)(row0 + r) * H + uu] = hn;
        }
        buf ^= 1; hb ^= 1;
    }
}

// ---------------------------------------------------------------------------
// LSTM3 + Dense: g_z[B,32] -> out[B,T,24]. 128 threads, C=2, shuffle gates,
// double-buffered hs; one barrier per step (dense reads the written buffer).
// ---------------------------------------------------------------------------
__global__ void __launch_bounds__(128, 2) lstm3_kernel(
    const float* __restrict__ W, const float* __restrict__ U,
    const float* __restrict__ b, const float* __restrict__ Wd,
    const float* __restrict__ bd, float* __restrict__ out, int B)
{
    constexpr int D = LAT, H = H3, G = 4 * H3, R = 8;
    constexpr int WDP = 68;
    __shared__ __align__(16) float zin[R][D];
    __shared__ __align__(16) float hs[2][R][H];
    __shared__ __align__(16) float wdst[FF][WDP];

    const int j    = threadIdx.x;
    const int uu   = j >> 1;
    const int par  = j & 1;
    const int sA   = (2 * par) * H + uu;
    const int sB   = (2 * par + 1) * H + uu;
    const int row0 = blockIdx.x * R;
    const int rlo  = 4 * par;

    u64 uA[H / 2], uB[H / 2];
#pragma unroll
    for (int k = 0; k < H / 2; k++) {
        uA[k] = pack2(U[(2 * k) * G + sA], U[(2 * k + 1) * G + sA]);
        uB[k] = pack2(U[(2 * k) * G + sB], U[(2 * k + 1) * G + sB]);
    }

    for (int idx = j; idx < H * FF; idx += 128) {
        int h = idx / FF, f = idx - h * FF;
        wdst[f][h] = Wd[idx];
    }
    for (int idx = j; idx < R * D; idx += 128) {
        int r = idx >> 5, k = idx & 31;
        int row = min(row0 + r, B - 1);
        zin[r][k] = g_z[(size_t)row * D + k];
    }
    for (int idx = j; idx < R * H; idx += 128) (&hs[0][0][0])[idx] = 0.0f;
    __syncthreads();

    // zw precompute (input constant over t)
    float zwA[R], zwB[R];
    {
        const float bvA = b[sA], bvB = b[sB];
#pragma unroll
        for (int r = 0; r < R; r++) { zwA[r] = bvA; zwB[r] = bvB; }
        for (int k = 0; k < D; k++) {
            const float wkA = W[k * G + sA], wkB = W[k * G + sB];
#pragma unroll
            for (int r = 0; r < R; r++) {
                zwA[r] += zin[r][k] * wkA;
                zwB[r] += zin[r][k] * wkB;
            }
        }
    }

    float cst[4] = {0.0f, 0.0f, 0.0f, 0.0f};

    // dense tasks: 192 over 128 threads: task j, and j+128 (j<64)
    const int d0f = j % FF, d0r = j / FF;
    const int d1f = (j + 128) % FF, d1r = (j + 128) / FF;
    const float bd0 = bd[d0f];
    const float bd1 = (j < 64) ? bd[d1f] : 0.0f;

    int hb = 0;
    for (int t = 0; t < TT; t++) {
        u64 accA[R], accB[R];
#pragma unroll
        for (int r = 0; r < R; r++) {
            accA[r] = pack2(zwA[r], 0.0f);
            accB[r] = pack2(zwB[r], 0.0f);
        }
#pragma unroll
        for (int k = 0; k < H / 4; k++) {
#pragma unroll
            for (int r = 0; r < R; r++) {
                const ulonglong2 hv = *(const ulonglong2*)&hs[hb][r][4 * k];
                accA[r] = ffma2(hv.x, uA[2 * k], accA[r]);
                accA[r] = ffma2(hv.y, uA[2 * k + 1], accA[r]);
                accB[r] = ffma2(hv.x, uB[2 * k], accB[r]);
                accB[r] = ffma2(hv.y, uB[2 * k + 1], accB[r]);
            }
        }
        float zA[R], zB[R];
#pragma unroll
        for (int r = 0; r < R; r++) {
            const float2 pA = unpack2(accA[r]);
            const float2 pB = unpack2(accB[r]);
            zA[r] = pA.x + pA.y;
            zB[r] = pB.x + pB.y;
        }
        float rA[4], rB[4];
#pragma unroll
        for (int k = 0; k < 4; k++) {
            float tA = par ? zA[k] : zA[k + 4];
            float tB = par ? zB[k] : zB[k + 4];
            rA[k] = __shfl_xor_sync(0xFFFFFFFFu, tA, 1);
            rB[k] = __shfl_xor_sync(0xFFFFFFFFu, tB, 1);
        }
#pragma unroll
        for (int k = 0; k < 4; k++) {
            const int r = rlo + k;
            const float iv = par ? rA[k] : zA[r];
            const float fv = par ? rB[k] : zB[r];
            const float gv = par ? zA[r] : rA[k];
            const float ov = par ? zB[r] : rB[k];
            cst[k] = sigmoidf(fv) * cst[k] + sigmoidf(iv) * fmaxf(gv, 0.0f);
            const float hn = sigmoidf(ov) * fmaxf(cst[k], 0.0f);
            hs[hb ^ 1][r][uu] = hn;
        }
        __syncthreads();   // S3: h(t) in hs[hb^1] visible for dense + next MMA

        // dense reads hs[hb^1]
        {
            int row = row0 + d0r;
            if (row < B) {
                u64 sacc = pack2(bd0, 0.0f);
#pragma unroll
                for (int k = 0; k < H / 4; k++) {
                    const ulonglong2 hv = *(const ulonglong2*)&hs[hb ^ 1][d0r][4 * k];
                    const ulonglong2 wv = *(const ulonglong2*)&wdst[d0f][4 * k];
                    sacc = ffma2(hv.x, wv.x, sacc);
                    sacc = ffma2(hv.y, wv.y, sacc);
                }
                const float2 p = unpack2(sacc);
                out[((size_t)row * TT + t) * FF + d0f] = p.x + p.y;
            }
        }
        if (j < 64) {
            int row = row0 + d1r;
            if (row < B) {
                u64 sacc = pack2(bd1, 0.0f);
#pragma unroll
                for (int k = 0; k < H / 4; k++) {
                    const ulonglong2 hv = *(const ulonglong2*)&hs[hb ^ 1][d1r][4 * k];
                    const ulonglong2 wv = *(const ulonglong2*)&wdst[d1f][4 * k];
                    sacc = ffma2(hv.x, wv.x, sacc);
                    sacc = ffma2(hv.y, wv.y, sacc);
                }
                const float2 p = unpack2(sacc);
                out[((size_t)row * TT + t) * FF + d1f] = p.x + p.y;
            }
        }
        hb ^= 1;
    }
}

// ---------------------------------------------------------------------------
extern "C" void kernel_launch(void* const* d_in, const int* in_sizes, int n_in,
                              void* d_out, int out_size)
{
    const float* x  = (const float*)d_in[0];
    const float* W1 = (const float*)d_in[1];
    const float* U1 = (const float*)d_in[2];
    const float* b1 = (const float*)d_in[3];
    const float* W2 = (const float*)d_in[4];
    const float* U2 = (const float*)d_in[5];
    const float* b2 = (const float*)d_in[6];
    const float* W3 = (const float*)d_in[7];
    const float* U3 = (const float*)d_in[8];
    const float* b3 = (const float*)d_in[9];
    const float* Wd = (const float*)d_in[10];
    const float* bd = (const float*)d_in[11];
    float* out = (float*)d_out;

    const int B = in_sizes[0] / (TT * FF);
    const int nblk = (B + 7) / 8;

    lstm1_kernel<<<nblk, 128>>>(x, W1, U1, b1, B);
    lstm2_kernel<<<nblk, 64>>>(W2, U2, b2, B);
    lstm3_kernel<<<nblk, 128>>>(W3, U3, b3, Wd, bd, out, B);
}